// round 3
// baseline (speedup 1.0000x reference)
#include <cuda_runtime.h>
#include <cstdint>

#define BATCH 32
#define H0 260
#define W0 1004
#define H1 258
#define W1W 1002
#define H1P 1004
#define H2 256
#define W2W 1000
#define D1 27
#define D2 45

__device__ float g_h1[(size_t)BATCH * 5 * H1 * H1P];
__device__ float g_rs[(size_t)BATCH * 5 * H1 * 3];
__device__ float g_Q1[BATCH * D1];
__device__ float g_Q2[BATCH * D2];
__device__ int   g_fh1[5];
__device__ int   g_fh2[5];
__device__ int   g_m1[BATCH * 5];
__device__ int   g_m2[BATCH * 5];

// ---------------- filter hashes (warp0: layer1, warp1: layer2) -------------
__global__ void k_filter_hash(const float* __restrict__ W1, const float* __restrict__ W2,
                              const float* __restrict__ a1, const float* __restrict__ b1,
                              const float* __restrict__ a2, const float* __restrict__ b2) {
    int t = threadIdx.x, lane = t & 31, wrp = t >> 5;
    const float* W = wrp ? W2 : W1;
    const float* a = wrp ? a2 : a1;
    float bb = wrp ? *b2 : *b1;
    int d = wrp ? D2 : D1;
    float ss = 0.f;
    if (lane < 5) for (int k = 0; k < d; ++k) { float v = W[lane * d + k]; ss += v * v; }
    float nrm = sqrtf(ss);
    for (int o = 16; o; o >>= 1) nrm = fmaxf(nrm, __shfl_xor_sync(0xffffffffu, nrm, o));
    float scale = 0.99f / nrm;
    if (lane < 5) {
        float dot = 0.f;
        for (int k = 0; k < d; ++k) dot += (W[lane * d + k] * scale) * a[k];
        float n2 = ss * scale * scale;
        float p2 = n2 * n2, p4 = p2 * p2, p8 = p4 * p4, p16 = p8 * p8;
        dot += n2 * a[d] + p2 * a[d + 1] + p4 * a[d + 2] + p8 * a[d + 3] + p16 * a[d + 4] + bb;
        int h = (int)floorf(dot / 0.1f);
        (wrp ? g_fh2 : g_fh1)[lane] = h & 1;
    }
}

// ---------------- patch means of x -> g_Q1. block = (b,c) ------------------
__global__ __launch_bounds__(256) void k_patch_mean_x(const float* __restrict__ x) {
    __shared__ float rs[H0 * 3];
    __shared__ double stot[3];
    int bc = blockIdx.x, b = bc / 3, c = bc % 3;
    int tid = threadIdx.x, lane = tid & 31, wrp = tid >> 5;
    for (int r = wrp; r < H0; r += 8) {
        const float* row = x + ((size_t)(b * 3 + c) * H0 + r) * W0;
        float s = 0.f;
        for (int col = lane; col < W0; col += 32) s += row[col];
        for (int o = 16; o; o >>= 1) s += __shfl_down_sync(0xffffffffu, s, o);
        if (lane == 0) {
            float e0 = row[0], e1 = row[1], ea = row[W0 - 2], eb = row[W0 - 1];
            rs[r * 3 + 0] = s - ea - eb;
            rs[r * 3 + 1] = s - e0 - eb;
            rs[r * 3 + 2] = s - e0 - e1;
        }
    }
    __syncthreads();
    if (tid < 3) { double tt = 0.0; for (int r = 0; r < H0; ++r) tt += (double)rs[r * 3 + tid]; stot[tid] = tt; }
    __syncthreads();
    if (tid < 9) {
        int i = tid / 3, j = tid % 3;
        double s = stot[j];
        if (i == 0) s -= (double)rs[258 * 3 + j] + (double)rs[259 * 3 + j];
        else if (i == 1) s -= (double)rs[0 * 3 + j] + (double)rs[259 * 3 + j];
        else s -= (double)rs[0 * 3 + j] + (double)rs[1 * 3 + j];
        g_Q1[b * D1 + c * 9 + tid] = (float)(s / (258.0 * 1002.0));
    }
}

// ---------------- query hash + mask, one thread per batch ------------------
__global__ void k_qmask(const float* __restrict__ a, const float* __restrict__ bp, int layer) {
    int b = threadIdx.x;
    if (b >= BATCH) return;
    int d = layer ? D2 : D1;
    const float* q = (layer ? g_Q2 : g_Q1) + b * d;
    const int* fh = layer ? g_fh2 : g_fh1;
    int* m = layer ? g_m2 : g_m1;
    float ss = 0.f;
    for (int k = 0; k < d; ++k) ss += q[k] * q[k];
    float inv = 1.0f / fmaxf(sqrtf(ss), 1e-12f);
    double dot = 0.0;
    for (int k = 0; k < d; ++k) dot += (double)(q[k] * inv) * (double)a[k];
    dot += 0.5 * ((double)a[d] + a[d + 1] + a[d + 2] + a[d + 3] + a[d + 4]) + (double)*bp;
    int qh = ((int)floor(dot / 0.1)) & 1;
    for (int c = 0; c < 5; ++c) m[b * 5 + c] = (fh[c] == qh) ? 1 : 0;
}

// ---------------- conv1 + relu + mask -> g_h1, row sums -> g_rs ------------
__global__ __launch_bounds__(256) void k_conv1(const float* __restrict__ x,
                                               const float* __restrict__ W1) {
    __shared__ float xs[9 * 1008];
    __shared__ float s_warp[8];
    __shared__ float s_ends[4];
    int bid = blockIdx.x, b = bid / H1, i = bid % H1;
    int tid = threadIdx.x, lane = tid & 31, wrp = tid >> 5;
    for (int idx = tid; idx < 9 * 1008; idx += 256) {
        int cc = idx / (3 * 1008), rem = idx - cc * 3 * 1008;
        int rr = rem / 1008, col = rem - rr * 1008;
        xs[idx] = (col < W0) ? x[((size_t)(b * 3 + cc) * H0 + (i + rr)) * W0 + col] : 0.f;
    }
    int m[5];
#pragma unroll
    for (int o = 0; o < 5; ++o) m[o] = g_m1[b * 5 + o];
    __syncthreads();
    int j0 = tid * 4;
    bool valid = (j0 < W1W);
    for (int o = 0; o < 5; ++o) {
        if (!m[o]) continue;
        float wr[27];
#pragma unroll
        for (int k = 0; k < 27; ++k) wr[k] = __ldg(W1 + o * 27 + k);
        float a0 = 0.f, a1v = 0.f, a2v = 0.f, a3v = 0.f;
        if (valid) {
#pragma unroll
            for (int cd = 0; cd < 9; ++cd) {
                const float* p = &xs[cd * 1008 + j0];
                float4 v4 = *(const float4*)p;
                float2 v2 = *(const float2*)(p + 4);
                float w0 = wr[cd * 3 + 0], w1 = wr[cd * 3 + 1], w2 = wr[cd * 3 + 2];
                a0  += v4.x * w0 + v4.y * w1 + v4.z * w2;
                a1v += v4.y * w0 + v4.z * w1 + v4.w * w2;
                a2v += v4.z * w0 + v4.w * w1 + v2.x * w2;
                a3v += v4.w * w0 + v2.x * w1 + v2.y * w2;
            }
        }
        float r0 = fmaxf(a0, 0.f), r1 = fmaxf(a1v, 0.f);
        float r2 = fmaxf(a2v, 0.f), r3 = fmaxf(a3v, 0.f);
        size_t rowbase = ((size_t)(b * 5 + o) * H1 + i) * H1P;
        float part = 0.f;
        if (valid) {
            if (j0 <= W1W - 4) {
                *(float4*)(g_h1 + rowbase + j0) = make_float4(r0, r1, r2, r3);
                part = r0 + r1 + r2 + r3;
            } else {
                g_h1[rowbase + 1000] = r0;
                g_h1[rowbase + 1001] = r1;
                part = r0 + r1;
            }
        }
        if (tid == 0)   { s_ends[0] = r0; s_ends[1] = r1; }
        if (tid == 250) { s_ends[2] = r0; s_ends[3] = r1; }
        for (int o2 = 16; o2; o2 >>= 1) part += __shfl_down_sync(0xffffffffu, part, o2);
        if (lane == 0) s_warp[wrp] = part;
        __syncthreads();
        if (tid == 0) {
            double full = 0.0;
#pragma unroll
            for (int k = 0; k < 8; ++k) full += (double)s_warp[k];
            double e0 = s_ends[0], e1 = s_ends[1], ea = s_ends[2], eb = s_ends[3];
            float* outp = g_rs + ((size_t)(b * 5 + o) * H1 + i) * 3;
            outp[0] = (float)(full - ea - eb);
            outp[1] = (float)(full - e0 - eb);
            outp[2] = (float)(full - e0 - e1);
        }
        __syncthreads();
    }
}

// ---------------- reduce g_rs -> g_Q2 patch means. block = (b,c) -----------
__global__ __launch_bounds__(256) void k_q2_reduce() {
    __shared__ double wred[8][3];
    int bc = blockIdx.x, b = bc / 5, c = bc % 5;
    int tid = threadIdx.x, lane = tid & 31, wrp = tid >> 5;
    if (!g_m1[b * 5 + c]) {
        if (tid < 9) g_Q2[b * D2 + c * 9 + tid] = 0.f;
        return;
    }
    const float* rsb = g_rs + ((size_t)(b * 5 + c)) * H1 * 3;
    double p0 = 0.0, p1 = 0.0, p2 = 0.0;
    for (int r = tid; r < H1; r += 256) {
        p0 += (double)rsb[r * 3 + 0]; p1 += (double)rsb[r * 3 + 1]; p2 += (double)rsb[r * 3 + 2];
    }
    for (int o = 16; o; o >>= 1) {
        p0 += __shfl_down_sync(0xffffffffu, p0, o);
        p1 += __shfl_down_sync(0xffffffffu, p1, o);
        p2 += __shfl_down_sync(0xffffffffu, p2, o);
    }
    if (lane == 0) { wred[wrp][0] = p0; wred[wrp][1] = p1; wred[wrp][2] = p2; }
    __syncthreads();
    if (tid == 0) {
        double tot[3] = {0.0, 0.0, 0.0};
        for (int k = 0; k < 8; ++k) { tot[0] += wred[k][0]; tot[1] += wred[k][1]; tot[2] += wred[k][2]; }
        const int rows[4] = {0, 1, 256, 257};
        double e[4][3];
        for (int k = 0; k < 4; ++k)
            for (int jo = 0; jo < 3; ++jo) e[k][jo] = (double)rsb[rows[k] * 3 + jo];
        const int exA[3] = {2, 0, 0};
        const int exB[3] = {3, 3, 1};
        for (int i = 0; i < 3; ++i)
            for (int jo = 0; jo < 3; ++jo)
                g_Q2[b * D2 + c * 9 + i * 3 + jo] =
                    (float)((tot[jo] - e[exA[i]][jo] - e[exB[i]][jo]) / 256000.0);
    }
}

// ---------------- conv2 + relu + mask + linear head ------------------------
#define K6_SMEM ((5 * 6 * H1P + 4 * 5 * W2W) * 4)

__global__ __launch_bounds__(256, 1) void k_conv2_linear(const float* __restrict__ W2,
                                                         const float* __restrict__ Wl,
                                                         const float* __restrict__ bl,
                                                         float* __restrict__ out) {
    extern __shared__ float sm[];
    float* tile = sm;                         // [na][6][1004]
    float* h2b = sm + 5 * 6 * H1P;            // [4][5][1000]
    __shared__ int clist[5], m2s[5], s_na;
    int bid = blockIdx.x, b = bid >> 6, i0 = (bid & 63) * 4;
    int tid = threadIdx.x, lane = tid & 31, wrp = tid >> 5;
    if (tid == 0) {
        int na = 0;
        for (int c = 0; c < 5; ++c) if (g_m1[b * 5 + c]) clist[na++] = c;
        s_na = na;
    }
    if (tid < 5) m2s[tid] = g_m2[b * 5 + tid];
    __syncthreads();
    int na = s_na;
    for (int idx = tid; idx < na * 6 * H1P; idx += 256) {
        int s = idx / (6 * H1P), rem = idx - s * 6 * H1P;
        int rr = rem / H1P, col = rem - rr * H1P;
        float v = 0.f;
        if (col < W1W) v = g_h1[((size_t)(b * 5 + clist[s]) * H1 + (i0 + rr)) * H1P + col];
        tile[idx] = v;
    }
    __syncthreads();
    int j0 = tid * 4;
    bool valid = (j0 < W2W);
    for (int o = 0; o < 5; ++o) {
        if (!m2s[o]) continue;
        float wr[45];
        for (int s = 0; s < na; ++s)
#pragma unroll
            for (int k = 0; k < 9; ++k) wr[s * 9 + k] = __ldg(&W2[o * 45 + clist[s] * 9 + k]);
#pragma unroll
        for (int ri = 0; ri < 4; ++ri) {
            float a0 = 0.f, a1v = 0.f, a2v = 0.f, a3v = 0.f;
            if (valid) {
                for (int s = 0; s < na; ++s) {
#pragma unroll
                    for (int di = 0; di < 3; ++di) {
                        const float* p = &tile[(s * 6 + ri + di) * H1P + j0];
                        float4 v4 = *(const float4*)p;
                        float2 v2 = *(const float2*)(p + 4);
                        float w0 = wr[s * 9 + di * 3 + 0];
                        float w1 = wr[s * 9 + di * 3 + 1];
                        float w2 = wr[s * 9 + di * 3 + 2];
                        a0  += v4.x * w0 + v4.y * w1 + v4.z * w2;
                        a1v += v4.y * w0 + v4.z * w1 + v4.w * w2;
                        a2v += v4.z * w0 + v4.w * w1 + v2.x * w2;
                        a3v += v4.w * w0 + v2.x * w1 + v2.y * w2;
                    }
                }
                float* hp = &h2b[(ri * 5 + o) * W2W + j0];
                hp[0] = fmaxf(a0, 0.f); hp[1] = fmaxf(a1v, 0.f);
                hp[2] = fmaxf(a2v, 0.f); hp[3] = fmaxf(a3v, 0.f);
            }
        }
    }
    __syncthreads();
    for (int p = wrp; p < 20; p += 8) {
        int ri = p / 5, c = p % 5;
        size_t obase = ((size_t)(b * 5 + c) * H2 + (i0 + ri)) * 10;
        if (!m2s[c]) {
            if (lane < 10) out[obase + lane] = __ldg(&bl[lane]);
            continue;
        }
        float acc[10];
#pragma unroll
        for (int t = 0; t < 10; ++t) acc[t] = 0.f;
        const float* hrow = &h2b[(ri * 5 + c) * W2W];
        for (int j = lane; j < W2W; j += 32) {
            float v = hrow[j];
#pragma unroll
            for (int t = 0; t < 10; ++t) acc[t] += v * __ldg(&Wl[t * 1000 + j]);
        }
#pragma unroll
        for (int t = 0; t < 10; ++t)
            for (int o = 16; o; o >>= 1) acc[t] += __shfl_down_sync(0xffffffffu, acc[t], o);
        if (lane == 0) {
#pragma unroll
            for (int t = 0; t < 10; ++t) out[obase + t] = acc[t] + __ldg(&bl[t]);
        }
    }
}

extern "C" void kernel_launch(void* const* d_in, const int* in_sizes, int n_in,
                              void* d_out, int out_size) {
    const float* x  = (const float*)d_in[0];
    const float* W1 = (const float*)d_in[1];
    const float* W2 = (const float*)d_in[2];
    const float* a1 = (const float*)d_in[3];
    const float* b1 = (const float*)d_in[4];
    const float* a2 = (const float*)d_in[5];
    const float* b2 = (const float*)d_in[6];
    const float* Wl = (const float*)d_in[7];
    const float* bl = (const float*)d_in[8];
    float* out = (float*)d_out;
    (void)in_sizes; (void)n_in; (void)out_size;

    cudaFuncSetAttribute(k_conv2_linear, cudaFuncAttributeMaxDynamicSharedMemorySize, K6_SMEM);

    k_filter_hash<<<1, 64>>>(W1, W2, a1, b1, a2, b2);
    k_patch_mean_x<<<BATCH * 3, 256>>>(x);
    k_qmask<<<1, 32>>>(a1, b1, 0);
    k_conv1<<<BATCH * H1, 256>>>(x, W1);
    k_q2_reduce<<<BATCH * 5, 256>>>();
    k_qmask<<<1, 32>>>(a2, b2, 1);
    k_conv2_linear<<<BATCH * 64, 256, K6_SMEM>>>(W2, Wl, bl, out);
}

// round 4
// speedup vs baseline: 1.7779x; 1.7779x over previous
#include <cuda_runtime.h>
#include <cstdint>

#define BATCH 32
#define H0 260
#define W0 1004
#define H1 258
#define W1W 1002
#define H1P 1004
#define H2 256
#define W2W 1000
#define D1 27
#define D2 45

__device__ float g_h1[(size_t)BATCH * 5 * H1 * H1P];
__device__ float g_h2[(size_t)BATCH * 5 * H2 * W2W];
__device__ float g_rs[(size_t)BATCH * 5 * H1 * 3];
__device__ float g_xrs[(size_t)BATCH * 3 * H0 * 3];
__device__ int   g_fh1[5];
__device__ int   g_fh2[5];
__device__ int   g_m1[BATCH * 5];
__device__ int   g_m2[BATCH * 5];

// ---------------- filter hashes (warp0: layer1, warp1: layer2) -------------
__global__ void k_filter_hash(const float* __restrict__ W1, const float* __restrict__ W2,
                              const float* __restrict__ a1, const float* __restrict__ b1,
                              const float* __restrict__ a2, const float* __restrict__ b2) {
    int t = threadIdx.x, lane = t & 31, wrp = t >> 5;
    const float* W = wrp ? W2 : W1;
    const float* a = wrp ? a2 : a1;
    float bb = wrp ? *b2 : *b1;
    int d = wrp ? D2 : D1;
    float ss = 0.f;
    if (lane < 5) for (int k = 0; k < d; ++k) { float v = W[lane * d + k]; ss += v * v; }
    float nrm = sqrtf(ss);
    for (int o = 16; o; o >>= 1) nrm = fmaxf(nrm, __shfl_xor_sync(0xffffffffu, nrm, o));
    float scale = 0.99f / nrm;
    if (lane < 5) {
        float dot = 0.f;
        for (int k = 0; k < d; ++k) dot += (W[lane * d + k] * scale) * a[k];
        float n2 = ss * scale * scale;
        float p2 = n2 * n2, p4 = p2 * p2, p8 = p4 * p4, p16 = p8 * p8;
        dot += n2 * a[d] + p2 * a[d + 1] + p4 * a[d + 2] + p8 * a[d + 3] + p16 * a[d + 4] + bb;
        int h = (int)floorf(dot / 0.1f);
        (wrp ? g_fh2 : g_fh1)[lane] = h & 1;
    }
}

// ---------------- x row restricted sums -> g_xrs. 384 blocks ---------------
__global__ __launch_bounds__(256) void k_xrows(const float* __restrict__ x) {
    int blk = blockIdx.x, bc = blk >> 2, q = blk & 3;
    int r0 = q * 65;
    int tid = threadIdx.x, lane = tid & 31, wrp = tid >> 5;
    for (int r = r0 + wrp; r < r0 + 65; r += 8) {
        const float* row = x + ((size_t)bc * H0 + r) * W0;
        float s = 0.f;
        for (int col = lane; col < W0; col += 32) s += row[col];
        for (int o = 16; o; o >>= 1) s += __shfl_down_sync(0xffffffffu, s, o);
        if (lane == 0) {
            float e0 = row[0], e1 = row[1], ea = row[W0 - 2], eb = row[W0 - 1];
            float* outp = g_xrs + ((size_t)bc * H0 + r) * 3;
            outp[0] = s - ea - eb;
            outp[1] = s - e0 - eb;
            outp[2] = s - e0 - e1;
        }
    }
}

// ---------------- layer-1 query hash + mask. one block per batch -----------
__global__ void k_q1mask(const float* __restrict__ a, const float* __restrict__ bp) {
    __shared__ float q[D1];
    int b = blockIdx.x, t = threadIdx.x;
    if (t < D1) {
        int c = t / 9, rem = t % 9, i = rem / 3, j = rem % 3;
        const float* base = g_xrs + ((size_t)(b * 3 + c) * H0) * 3;
        double s = 0.0;
        for (int r = i; r < i + 258; ++r) s += (double)base[r * 3 + j];
        q[t] = (float)(s / (258.0 * 1002.0));
    }
    __syncthreads();
    if (t == 0) {
        float ss = 0.f;
        for (int k = 0; k < D1; ++k) ss += q[k] * q[k];
        float inv = 1.0f / fmaxf(sqrtf(ss), 1e-12f);
        double dot = 0.0;
        for (int k = 0; k < D1; ++k) dot += (double)(q[k] * inv) * (double)a[k];
        dot += 0.5 * ((double)a[D1] + a[D1 + 1] + a[D1 + 2] + a[D1 + 3] + a[D1 + 4]) + (double)*bp;
        int qh = ((int)floor(dot / 0.1)) & 1;
        for (int c = 0; c < 5; ++c) g_m1[b * 5 + c] = (g_fh1[c] == qh) ? 1 : 0;
    }
}

// ---------------- conv1: 6 rows/block, register rotation -------------------
#define C1_SMEM (3 * 8 * 1008 * 4)

__global__ __launch_bounds__(256, 2) void k_conv1(const float* __restrict__ x,
                                                  const float* __restrict__ W1) {
    extern __shared__ float xs[];            // [3][8][1008]
    __shared__ float s_warp[8][6];
    __shared__ float s_ends[6][4];
    int bid = blockIdx.x, b = bid / 43, g = bid % 43, i0 = g * 6;
    int tid = threadIdx.x, lane = tid & 31, wrp = tid >> 5;
    for (int idx = tid; idx < 3 * 8 * 1008; idx += 256) {
        int cc = idx / 8064, rem = idx - cc * 8064;
        int rr = rem / 1008, col = rem - rr * 1008;
        xs[idx] = (col < W0) ? x[((size_t)(b * 3 + cc) * H0 + (i0 + rr)) * W0 + col] : 0.f;
    }
    int m[5];
#pragma unroll
    for (int o = 0; o < 5; ++o) m[o] = g_m1[b * 5 + o];
    __syncthreads();
    int j0 = tid * 4;
    bool valid = (j0 < W1W);
    for (int o = 0; o < 5; ++o) {
        if (!m[o]) continue;
        float wr[27];
#pragma unroll
        for (int k = 0; k < 27; ++k) wr[k] = __ldg(W1 + o * 27 + k);
        float acc[6][4];
#pragma unroll
        for (int ri = 0; ri < 6; ++ri)
#pragma unroll
            for (int k = 0; k < 4; ++k) acc[ri][k] = 0.f;
        if (valid) {
#pragma unroll
            for (int cc = 0; cc < 3; ++cc) {
#pragma unroll
                for (int rr = 0; rr < 8; ++rr) {
                    const float* p = &xs[(cc * 8 + rr) * 1008 + j0];
                    float4 v4 = *(const float4*)p;
                    float2 v2 = *(const float2*)(p + 4);
#pragma unroll
                    for (int di = 0; di < 3; ++di) {
                        int ri = rr - di;
                        if (ri >= 0 && ri < 6) {
                            float w0 = wr[cc * 9 + di * 3 + 0];
                            float w1 = wr[cc * 9 + di * 3 + 1];
                            float w2 = wr[cc * 9 + di * 3 + 2];
                            acc[ri][0] += v4.x * w0 + v4.y * w1 + v4.z * w2;
                            acc[ri][1] += v4.y * w0 + v4.z * w1 + v4.w * w2;
                            acc[ri][2] += v4.z * w0 + v4.w * w1 + v2.x * w2;
                            acc[ri][3] += v4.w * w0 + v2.x * w1 + v2.y * w2;
                        }
                    }
                }
            }
        }
#pragma unroll
        for (int ri = 0; ri < 6; ++ri) {
            float r0 = fmaxf(acc[ri][0], 0.f), r1 = fmaxf(acc[ri][1], 0.f);
            float r2 = fmaxf(acc[ri][2], 0.f), r3 = fmaxf(acc[ri][3], 0.f);
            size_t rowbase = ((size_t)(b * 5 + o) * H1 + (i0 + ri)) * H1P;
            float part = 0.f;
            if (valid) {
                if (j0 <= W1W - 4) {
                    *(float4*)(g_h1 + rowbase + j0) = make_float4(r0, r1, r2, r3);
                    part = r0 + r1 + r2 + r3;
                } else {
                    g_h1[rowbase + 1000] = r0;
                    g_h1[rowbase + 1001] = r1;
                    part = r0 + r1;
                }
            }
            if (tid == 0)   { s_ends[ri][0] = r0; s_ends[ri][1] = r1; }
            if (tid == 250) { s_ends[ri][2] = r0; s_ends[ri][3] = r1; }
            for (int o2 = 16; o2; o2 >>= 1) part += __shfl_down_sync(0xffffffffu, part, o2);
            if (lane == 0) s_warp[wrp][ri] = part;
        }
        __syncthreads();
        if (tid < 6) {
            double full = 0.0;
#pragma unroll
            for (int k = 0; k < 8; ++k) full += (double)s_warp[k][tid];
            double e0 = s_ends[tid][0], e1 = s_ends[tid][1];
            double ea = s_ends[tid][2], eb = s_ends[tid][3];
            float* outp = g_rs + ((size_t)(b * 5 + o) * H1 + (i0 + tid)) * 3;
            outp[0] = (float)(full - ea - eb);
            outp[1] = (float)(full - e0 - eb);
            outp[2] = (float)(full - e0 - e1);
        }
        __syncthreads();
    }
}

// ---------------- layer-2 query hash + mask. one block per batch -----------
__global__ void k_q2mask(const float* __restrict__ a, const float* __restrict__ bp) {
    __shared__ float q[D2];
    int b = blockIdx.x, tid = threadIdx.x, lane = tid & 31, c = tid >> 5;
    if (c < 5) {
        if (!g_m1[b * 5 + c]) {
            if (lane < 9) q[c * 9 + lane] = 0.f;
        } else {
            const float* rsb = g_rs + ((size_t)(b * 5 + c)) * H1 * 3;
            double p0 = 0.0, p1 = 0.0, p2 = 0.0;
            for (int r = lane; r < H1; r += 32) {
                p0 += (double)rsb[r * 3 + 0];
                p1 += (double)rsb[r * 3 + 1];
                p2 += (double)rsb[r * 3 + 2];
            }
            for (int o = 16; o; o >>= 1) {
                p0 += __shfl_down_sync(0xffffffffu, p0, o);
                p1 += __shfl_down_sync(0xffffffffu, p1, o);
                p2 += __shfl_down_sync(0xffffffffu, p2, o);
            }
            if (lane == 0) {
                double tot[3] = {p0, p1, p2};
                const int rows[4] = {0, 1, 256, 257};
                double e[4][3];
                for (int k = 0; k < 4; ++k)
                    for (int jo = 0; jo < 3; ++jo) e[k][jo] = (double)rsb[rows[k] * 3 + jo];
                const int exA[3] = {2, 0, 0};
                const int exB[3] = {3, 3, 1};
                for (int i = 0; i < 3; ++i)
                    for (int jo = 0; jo < 3; ++jo)
                        q[c * 9 + i * 3 + jo] =
                            (float)((tot[jo] - e[exA[i]][jo] - e[exB[i]][jo]) / 256000.0);
            }
        }
    }
    __syncthreads();
    if (tid == 0) {
        float ss = 0.f;
        for (int k = 0; k < D2; ++k) ss += q[k] * q[k];
        float inv = 1.0f / fmaxf(sqrtf(ss), 1e-12f);
        double dot = 0.0;
        for (int k = 0; k < D2; ++k) dot += (double)(q[k] * inv) * (double)a[k];
        dot += 0.5 * ((double)a[D2] + a[D2 + 1] + a[D2 + 2] + a[D2 + 3] + a[D2 + 4]) + (double)*bp;
        int qh = ((int)floor(dot / 0.1)) & 1;
        for (int cc = 0; cc < 5; ++cc) g_m2[b * 5 + cc] = (g_fh2[cc] == qh) ? 1 : 0;
    }
}

// ---------------- conv2: 8 rows/block, 512 threads, h2 -> gmem -------------
#define C2_SMEM (5 * 10 * H1P * 4)

__global__ __launch_bounds__(512, 1) void k_conv2(const float* __restrict__ W2) {
    extern __shared__ float ts[];             // [na][10][1004]
    __shared__ int clist[5], m2s[5], s_na;
    int bid = blockIdx.x, b = bid >> 5, i0 = (bid & 31) * 8;
    int tid = threadIdx.x;
    if (tid == 0) {
        int na = 0;
        for (int c = 0; c < 5; ++c) if (g_m1[b * 5 + c]) clist[na++] = c;
        s_na = na;
    }
    if (tid < 5) m2s[tid] = g_m2[b * 5 + tid];
    __syncthreads();
    int na = s_na;
    for (int idx = tid; idx < na * 10 * H1P; idx += 512) {
        int s = idx / (10 * H1P), rem = idx - s * 10 * H1P;
        int rr = rem / H1P, col = rem - rr * H1P;
        ts[idx] = (col < W1W) ? g_h1[((size_t)(b * 5 + clist[s]) * H1 + (i0 + rr)) * H1P + col] : 0.f;
    }
    __syncthreads();
    int half = tid >> 8, t2 = tid & 255;
    int j0 = t2 * 4;
    bool valid = (j0 < W2W);
    int rbase = half * 4;
    for (int o = 0; o < 5; ++o) {
        if (!m2s[o]) continue;
        float acc[4][4];
#pragma unroll
        for (int ri = 0; ri < 4; ++ri)
#pragma unroll
            for (int k = 0; k < 4; ++k) acc[ri][k] = 0.f;
        if (valid) {
            for (int s = 0; s < na; ++s) {
                float wr[9];
#pragma unroll
                for (int k = 0; k < 9; ++k) wr[k] = __ldg(&W2[o * 45 + clist[s] * 9 + k]);
#pragma unroll
                for (int rr = 0; rr < 6; ++rr) {
                    const float* p = &ts[(s * 10 + rbase + rr) * H1P + j0];
                    float4 v4 = *(const float4*)p;
                    float2 v2 = *(const float2*)(p + 4);
#pragma unroll
                    for (int di = 0; di < 3; ++di) {
                        int ri = rr - di;
                        if (ri >= 0 && ri < 4) {
                            float w0 = wr[di * 3 + 0];
                            float w1 = wr[di * 3 + 1];
                            float w2 = wr[di * 3 + 2];
                            acc[ri][0] += v4.x * w0 + v4.y * w1 + v4.z * w2;
                            acc[ri][1] += v4.y * w0 + v4.z * w1 + v4.w * w2;
                            acc[ri][2] += v4.z * w0 + v4.w * w1 + v2.x * w2;
                            acc[ri][3] += v4.w * w0 + v2.x * w1 + v2.y * w2;
                        }
                    }
                }
            }
        }
        if (valid) {
#pragma unroll
            for (int ri = 0; ri < 4; ++ri) {
                float4 v = make_float4(fmaxf(acc[ri][0], 0.f), fmaxf(acc[ri][1], 0.f),
                                       fmaxf(acc[ri][2], 0.f), fmaxf(acc[ri][3], 0.f));
                *(float4*)&g_h2[((size_t)(b * 5 + o) * H2 + (i0 + rbase + ri)) * W2W + j0] = v;
            }
        }
    }
}

// ---------------- linear head: h2 @ Wl^T + bl ------------------------------
__global__ __launch_bounds__(256) void k_linear(const float* __restrict__ Wl,
                                                const float* __restrict__ bl,
                                                float* __restrict__ out) {
    __shared__ float wl_s[W2W * 10];           // transposed [j][t], 40 KB
    int bid = blockIdx.x, bc = bid >> 3, rg = (bid & 7) * 32;
    int b = bc / 5, c = bc % 5;
    int tid = threadIdx.x, lane = tid & 31, wrp = tid >> 5;
    int m = g_m2[b * 5 + c];
    if (m) {
        for (int idx = tid; idx < W2W * 10; idx += 256) {
            int t = idx / W2W, j = idx - t * W2W;
            wl_s[j * 10 + t] = Wl[idx];
        }
    }
    __syncthreads();
    for (int k = 0; k < 4; ++k) {
        int row = rg + wrp * 4 + k;
        size_t obase = ((size_t)(b * 5 + c) * H2 + row) * 10;
        if (!m) {
            if (lane < 10) out[obase + lane] = __ldg(&bl[lane]);
            continue;
        }
        float acc[10];
#pragma unroll
        for (int t = 0; t < 10; ++t) acc[t] = 0.f;
        const float* hrow = &g_h2[((size_t)(b * 5 + c) * H2 + row) * W2W];
        for (int j = lane; j < W2W; j += 32) {
            float v = hrow[j];
            const float* w = &wl_s[j * 10];
#pragma unroll
            for (int t = 0; t < 10; ++t) acc[t] += v * w[t];
        }
#pragma unroll
        for (int t = 0; t < 10; ++t)
            for (int o = 16; o; o >>= 1) acc[t] += __shfl_down_sync(0xffffffffu, acc[t], o);
        if (lane == 0) {
#pragma unroll
            for (int t = 0; t < 10; ++t) out[obase + t] = acc[t] + __ldg(&bl[t]);
        }
    }
}

extern "C" void kernel_launch(void* const* d_in, const int* in_sizes, int n_in,
                              void* d_out, int out_size) {
    const float* x  = (const float*)d_in[0];
    const float* W1 = (const float*)d_in[1];
    const float* W2 = (const float*)d_in[2];
    const float* a1 = (const float*)d_in[3];
    const float* b1 = (const float*)d_in[4];
    const float* a2 = (const float*)d_in[5];
    const float* b2 = (const float*)d_in[6];
    const float* Wl = (const float*)d_in[7];
    const float* bl = (const float*)d_in[8];
    float* out = (float*)d_out;
    (void)in_sizes; (void)n_in; (void)out_size;

    cudaFuncSetAttribute(k_conv1, cudaFuncAttributeMaxDynamicSharedMemorySize, C1_SMEM);
    cudaFuncSetAttribute(k_conv2, cudaFuncAttributeMaxDynamicSharedMemorySize, C2_SMEM);

    k_filter_hash<<<1, 64>>>(W1, W2, a1, b1, a2, b2);
    k_xrows<<<BATCH * 3 * 4, 256>>>(x);
    k_q1mask<<<BATCH, 32>>>(a1, b1);
    k_conv1<<<BATCH * 43, 256, C1_SMEM>>>(x, W1);
    k_q2mask<<<BATCH, 160>>>(a2, b2);
    k_conv2<<<BATCH * 32, 512, C2_SMEM>>>(W2);
    k_linear<<<BATCH * 5 * 8, 256>>>(Wl, bl, out);
}

// round 5
// speedup vs baseline: 3.1824x; 1.7900x over previous
#include <cuda_runtime.h>
#include <cstdint>

#define BATCH 32
#define H0 260
#define W0 1004
#define H1 258
#define W1W 1002
#define H1P 1004
#define H2 256
#define W2W 1000
#define D1 27
#define D2 45

__device__ float g_h1[(size_t)BATCH * 5 * H1 * H1P];
__device__ float g_h2[(size_t)BATCH * 5 * H2 * W2W];
__device__ float g_rsp[(size_t)BATCH * 5 * H1 * 2];   // per-half row partial sums
__device__ float g_re[(size_t)BATCH * 5 * H1 * 4];    // row edges e0,e1,e1000,e1001
__device__ float g_xrs[(size_t)BATCH * 3 * H0 * 3];
__device__ int   g_fh1[5];
__device__ int   g_fh2[5];
__device__ int   g_m1[BATCH * 5];
__device__ int   g_m2[BATCH * 5];

// ---------------- filter hashes (warp0: layer1, warp1: layer2) -------------
__global__ void k_filter_hash(const float* __restrict__ W1, const float* __restrict__ W2,
                              const float* __restrict__ a1, const float* __restrict__ b1,
                              const float* __restrict__ a2, const float* __restrict__ b2) {
    int t = threadIdx.x, lane = t & 31, wrp = t >> 5;
    const float* W = wrp ? W2 : W1;
    const float* a = wrp ? a2 : a1;
    float bb = wrp ? *b2 : *b1;
    int d = wrp ? D2 : D1;
    float ss = 0.f;
    if (lane < 5) for (int k = 0; k < d; ++k) { float v = W[lane * d + k]; ss += v * v; }
    float nrm = sqrtf(ss);
    for (int o = 16; o; o >>= 1) nrm = fmaxf(nrm, __shfl_xor_sync(0xffffffffu, nrm, o));
    float scale = 0.99f / nrm;
    if (lane < 5) {
        float dot = 0.f;
        for (int k = 0; k < d; ++k) dot += (W[lane * d + k] * scale) * a[k];
        float n2 = ss * scale * scale;
        float p2 = n2 * n2, p4 = p2 * p2, p8 = p4 * p4, p16 = p8 * p8;
        dot += n2 * a[d] + p2 * a[d + 1] + p4 * a[d + 2] + p8 * a[d + 3] + p16 * a[d + 4] + bb;
        int h = (int)floorf(dot / 0.1f);
        (wrp ? g_fh2 : g_fh1)[lane] = h & 1;
    }
}

// ---------------- x row restricted sums -> g_xrs ---------------------------
__global__ __launch_bounds__(256) void k_xrows(const float* __restrict__ x) {
    int blk = blockIdx.x, bc = blk >> 2, q = blk & 3;
    int r0 = q * 65;
    int tid = threadIdx.x, lane = tid & 31, wrp = tid >> 5;
    for (int r = r0 + wrp; r < r0 + 65; r += 8) {
        const float* row = x + ((size_t)bc * H0 + r) * W0;
        float s = 0.f;
        for (int col = lane; col < W0; col += 32) s += row[col];
        for (int o = 16; o; o >>= 1) s += __shfl_down_sync(0xffffffffu, s, o);
        if (lane == 0) {
            float e0 = row[0], e1 = row[1], ea = row[W0 - 2], eb = row[W0 - 1];
            float* outp = g_xrs + ((size_t)bc * H0 + r) * 3;
            outp[0] = s - ea - eb;
            outp[1] = s - e0 - eb;
            outp[2] = s - e0 - e1;
        }
    }
}

// ---------------- layer-1 query hash + mask --------------------------------
__global__ void k_q1mask(const float* __restrict__ a, const float* __restrict__ bp) {
    __shared__ float q[D1];
    int b = blockIdx.x, t = threadIdx.x;
    if (t < D1) {
        int c = t / 9, rem = t % 9, i = rem / 3, j = rem % 3;
        const float* base = g_xrs + ((size_t)(b * 3 + c) * H0) * 3;
        double s = 0.0;
        for (int r = i; r < i + 258; ++r) s += (double)base[r * 3 + j];
        q[t] = (float)(s / (258.0 * 1002.0));
    }
    __syncthreads();
    if (t == 0) {
        float ss = 0.f;
        for (int k = 0; k < D1; ++k) ss += q[k] * q[k];
        float inv = 1.0f / fmaxf(sqrtf(ss), 1e-12f);
        double dot = 0.0;
        for (int k = 0; k < D1; ++k) dot += (double)(q[k] * inv) * (double)a[k];
        dot += 0.5 * ((double)a[D1] + a[D1 + 1] + a[D1 + 2] + a[D1 + 3] + a[D1 + 4]) + (double)*bp;
        int qh = ((int)floor(dot / 0.1)) & 1;
        for (int c = 0; c < 5; ++c) g_m1[b * 5 + c] = (g_fh1[c] == qh) ? 1 : 0;
    }
}

// ---------------- conv1: 6 rows x half-width per block ---------------------
#define C1_SMEM (3 * 8 * 512 * 4)

__global__ __launch_bounds__(128, 4) void k_conv1(const float* __restrict__ x,
                                                  const float* __restrict__ W1) {
    extern __shared__ float xs[];            // [3][8][512]
    __shared__ float s_warp[4][6];
    __shared__ float sE[6][2];
    int bid = blockIdx.x;
    int b = bid / 86, rem2 = bid % 86;
    int g = rem2 >> 1, half = rem2 & 1;
    int i0 = g * 6, base = half * 500;
    int tid = threadIdx.x, lane = tid & 31, wrp = tid >> 5;

    for (int v = tid; v < 3 * 8 * 128; v += 128) {
        int cc = v >> 10, rm = v & 1023;
        int rr = rm >> 7, jj = rm & 127;
        int col = base + jj * 4;
        float4 val = make_float4(0.f, 0.f, 0.f, 0.f);
        if (col + 3 < W0)
            val = *(const float4*)&x[((size_t)(b * 3 + cc) * H0 + (i0 + rr)) * W0 + col];
        ((float4*)xs)[v] = val;
    }
    int m[5];
#pragma unroll
    for (int o = 0; o < 5; ++o) m[o] = g_m1[b * 5 + o];
    __syncthreads();

    int nfull = half ? 125 : 125;                  // threads with 4 full cols
    bool tail = (half == 1 && tid == 125);          // cols 1000,1001
    bool valid = (tid < nfull) || tail;
    int j0 = tid * 4;

    for (int o = 0; o < 5; ++o) {
        if (!m[o]) continue;
        float acc[6][4];
#pragma unroll
        for (int ri = 0; ri < 6; ++ri)
#pragma unroll
            for (int k = 0; k < 4; ++k) acc[ri][k] = 0.f;
        if (valid) {
#pragma unroll
            for (int cc = 0; cc < 3; ++cc) {
                float wr[9];
#pragma unroll
                for (int k = 0; k < 9; ++k) wr[k] = __ldg(W1 + o * 27 + cc * 9 + k);
#pragma unroll
                for (int rr = 0; rr < 8; ++rr) {
                    const float* p = &xs[(cc * 8 + rr) * 512 + j0];
                    float4 v4 = *(const float4*)p;
                    float2 v2 = *(const float2*)(p + 4);
#pragma unroll
                    for (int di = 0; di < 3; ++di) {
                        int ri = rr - di;
                        if (ri >= 0 && ri < 6) {
                            float w0 = wr[di * 3 + 0], w1 = wr[di * 3 + 1], w2 = wr[di * 3 + 2];
                            acc[ri][0] += v4.x * w0 + v4.y * w1 + v4.z * w2;
                            acc[ri][1] += v4.y * w0 + v4.z * w1 + v4.w * w2;
                            acc[ri][2] += v4.z * w0 + v4.w * w1 + v2.x * w2;
                            acc[ri][3] += v4.w * w0 + v2.x * w1 + v2.y * w2;
                        }
                    }
                }
            }
        }
#pragma unroll
        for (int ri = 0; ri < 6; ++ri) {
            float r0 = fmaxf(acc[ri][0], 0.f), r1 = fmaxf(acc[ri][1], 0.f);
            float r2 = fmaxf(acc[ri][2], 0.f), r3 = fmaxf(acc[ri][3], 0.f);
            float part = 0.f;
            if (valid) {
                size_t rowbase = ((size_t)(b * 5 + o) * H1 + (i0 + ri)) * H1P + base + j0;
                if (!tail) {
                    *(float4*)(g_h1 + rowbase) = make_float4(r0, r1, r2, r3);
                    part = r0 + r1 + r2 + r3;
                } else {
                    g_h1[rowbase + 0] = r0;
                    g_h1[rowbase + 1] = r1;
                    part = r0 + r1;
                }
            }
            if (half == 0 && tid == 0)   { sE[ri][0] = r0; sE[ri][1] = r1; }
            if (half == 1 && tid == 125) { sE[ri][0] = r0; sE[ri][1] = r1; }
            for (int o2 = 16; o2; o2 >>= 1) part += __shfl_down_sync(0xffffffffu, part, o2);
            if (lane == 0) s_warp[wrp][ri] = part;
        }
        __syncthreads();
        if (tid < 6) {
            float full = s_warp[0][tid] + s_warp[1][tid] + s_warp[2][tid] + s_warp[3][tid];
            size_t row = (size_t)(b * 5 + o) * H1 + (i0 + tid);
            g_rsp[row * 2 + half] = full;
            g_re[row * 4 + half * 2 + 0] = sE[tid][0];
            g_re[row * 4 + half * 2 + 1] = sE[tid][1];
        }
        __syncthreads();
    }
}

// ---------------- layer-2 query hash + mask --------------------------------
__global__ void k_q2mask(const float* __restrict__ a, const float* __restrict__ bp) {
    __shared__ float q[D2];
    int b = blockIdx.x, tid = threadIdx.x, lane = tid & 31, c = tid >> 5;
    if (c < 5) {
        if (!g_m1[b * 5 + c]) {
            if (lane < 9) q[c * 9 + lane] = 0.f;
        } else {
            const float* P = g_rsp + (size_t)(b * 5 + c) * H1 * 2;
            const float* E = g_re + (size_t)(b * 5 + c) * H1 * 4;
            double F = 0.0, E0 = 0.0, E1 = 0.0, EA = 0.0, EB = 0.0;
            for (int r = lane; r < H1; r += 32) {
                F  += (double)P[r * 2 + 0] + (double)P[r * 2 + 1];
                E0 += (double)E[r * 4 + 0];
                E1 += (double)E[r * 4 + 1];
                EA += (double)E[r * 4 + 2];
                EB += (double)E[r * 4 + 3];
            }
            for (int o = 16; o; o >>= 1) {
                F  += __shfl_down_sync(0xffffffffu, F, o);
                E0 += __shfl_down_sync(0xffffffffu, E0, o);
                E1 += __shfl_down_sync(0xffffffffu, E1, o);
                EA += __shfl_down_sync(0xffffffffu, EA, o);
                EB += __shfl_down_sync(0xffffffffu, EB, o);
            }
            if (lane == 0) {
                double tot[3] = {F - EA - EB, F - E0 - EB, F - E0 - E1};
                const int rows[4] = {0, 1, 256, 257};
                double rsv[4][3];
                for (int k = 0; k < 4; ++k) {
                    int r = rows[k];
                    double fr = (double)P[r * 2 + 0] + (double)P[r * 2 + 1];
                    double e0 = E[r * 4 + 0], e1 = E[r * 4 + 1];
                    double ea = E[r * 4 + 2], eb = E[r * 4 + 3];
                    rsv[k][0] = fr - ea - eb;
                    rsv[k][1] = fr - e0 - eb;
                    rsv[k][2] = fr - e0 - e1;
                }
                const int exA[3] = {2, 0, 0};
                const int exB[3] = {3, 3, 1};
                for (int i = 0; i < 3; ++i)
                    for (int jo = 0; jo < 3; ++jo)
                        q[c * 9 + i * 3 + jo] =
                            (float)((tot[jo] - rsv[exA[i]][jo] - rsv[exB[i]][jo]) / 256000.0);
            }
        }
    }
    __syncthreads();
    if (tid == 0) {
        float ss = 0.f;
        for (int k = 0; k < D2; ++k) ss += q[k] * q[k];
        float inv = 1.0f / fmaxf(sqrtf(ss), 1e-12f);
        double dot = 0.0;
        for (int k = 0; k < D2; ++k) dot += (double)(q[k] * inv) * (double)a[k];
        dot += 0.5 * ((double)a[D2] + a[D2 + 1] + a[D2 + 2] + a[D2 + 3] + a[D2 + 4]) + (double)*bp;
        int qh = ((int)floor(dot / 0.1)) & 1;
        for (int cc = 0; cc < 5; ++cc) g_m2[b * 5 + cc] = (g_fh2[cc] == qh) ? 1 : 0;
    }
}

// ---------------- conv2: 8 rows x half-width, 512 threads ------------------
#define C2_SMEM (5 * 10 * 512 * 4)

__global__ __launch_bounds__(512, 2) void k_conv2(const float* __restrict__ W2) {
    extern __shared__ float ts[];             // [na][10][512]
    __shared__ int clist[5], m2s[5], s_na;
    int bid = blockIdx.x;
    int b = bid >> 6, rem2 = bid & 63;
    int g = rem2 >> 1, half = rem2 & 1;
    int i0 = g * 8, base = half * 500;
    int tid = threadIdx.x;
    if (tid == 0) {
        int na = 0;
        for (int c = 0; c < 5; ++c) if (g_m1[b * 5 + c]) clist[na++] = c;
        s_na = na;
    }
    if (tid < 5) m2s[tid] = g_m2[b * 5 + tid];
    __syncthreads();
    int na = s_na;
    for (int v = tid; v < na * 10 * 128; v += 512) {
        int s = v / 1280, rm = v - s * 1280;
        int rr = rm >> 7, jj = rm & 127;
        int col = base + jj * 4;
        float4 val = make_float4(0.f, 0.f, 0.f, 0.f);
        if (col + 3 < H1P)
            val = *(const float4*)&g_h1[((size_t)(b * 5 + clist[s]) * H1 + (i0 + rr)) * H1P + col];
        ((float4*)ts)[v] = val;
    }
    __syncthreads();
    int quad = tid >> 7, t2 = tid & 127;
    int rbase = quad * 2;
    int j0 = t2 * 4;
    bool valid = (t2 < 125);
    for (int o = 0; o < 5; ++o) {
        if (!m2s[o]) continue;
        float acc[2][4];
#pragma unroll
        for (int ri = 0; ri < 2; ++ri)
#pragma unroll
            for (int k = 0; k < 4; ++k) acc[ri][k] = 0.f;
        if (valid) {
            for (int s = 0; s < na; ++s) {
                float wr[9];
#pragma unroll
                for (int k = 0; k < 9; ++k) wr[k] = __ldg(&W2[o * 45 + clist[s] * 9 + k]);
#pragma unroll
                for (int rr = 0; rr < 4; ++rr) {
                    const float* p = &ts[(s * 10 + rbase + rr) * 512 + j0];
                    float4 v4 = *(const float4*)p;
                    float2 v2 = *(const float2*)(p + 4);
#pragma unroll
                    for (int di = 0; di < 3; ++di) {
                        int ri = rr - di;
                        if (ri >= 0 && ri < 2) {
                            float w0 = wr[di * 3 + 0], w1 = wr[di * 3 + 1], w2 = wr[di * 3 + 2];
                            acc[ri][0] += v4.x * w0 + v4.y * w1 + v4.z * w2;
                            acc[ri][1] += v4.y * w0 + v4.z * w1 + v4.w * w2;
                            acc[ri][2] += v4.z * w0 + v4.w * w1 + v2.x * w2;
                            acc[ri][3] += v4.w * w0 + v2.x * w1 + v2.y * w2;
                        }
                    }
                }
            }
#pragma unroll
            for (int ri = 0; ri < 2; ++ri) {
                float4 v = make_float4(fmaxf(acc[ri][0], 0.f), fmaxf(acc[ri][1], 0.f),
                                       fmaxf(acc[ri][2], 0.f), fmaxf(acc[ri][3], 0.f));
                *(float4*)&g_h2[((size_t)(b * 5 + o) * H2 + (i0 + rbase + ri)) * W2W + base + j0] = v;
            }
        }
    }
}

// ---------------- linear head: h2 @ Wl^T + bl ------------------------------
__global__ __launch_bounds__(256) void k_linear(const float* __restrict__ Wl,
                                                const float* __restrict__ bl,
                                                float* __restrict__ out) {
    __shared__ float wl_s[W2W * 10];           // transposed [j][t], 40 KB
    int bid = blockIdx.x, bc = bid >> 3, rg = (bid & 7) * 32;
    int b = bc / 5, c = bc % 5;
    int tid = threadIdx.x, lane = tid & 31, wrp = tid >> 5;
    int m = g_m2[b * 5 + c];
    if (m) {
        for (int idx = tid; idx < W2W * 10; idx += 256) {
            int t = idx / W2W, j = idx - t * W2W;
            wl_s[j * 10 + t] = Wl[idx];
        }
    }
    __syncthreads();
    for (int k = 0; k < 4; ++k) {
        int row = rg + wrp * 4 + k;
        size_t obase = ((size_t)(b * 5 + c) * H2 + row) * 10;
        if (!m) {
            if (lane < 10) out[obase + lane] = __ldg(&bl[lane]);
            continue;
        }
        float acc[10];
#pragma unroll
        for (int t = 0; t < 10; ++t) acc[t] = 0.f;
        const float* hrow = &g_h2[((size_t)(b * 5 + c) * H2 + row) * W2W];
        for (int j = lane; j < W2W; j += 32) {
            float v = hrow[j];
            const float* w = &wl_s[j * 10];
#pragma unroll
            for (int t = 0; t < 10; ++t) acc[t] += v * w[t];
        }
#pragma unroll
        for (int t = 0; t < 10; ++t)
            for (int o = 16; o; o >>= 1) acc[t] += __shfl_down_sync(0xffffffffu, acc[t], o);
        if (lane == 0) {
#pragma unroll
            for (int t = 0; t < 10; ++t) out[obase + t] = acc[t] + __ldg(&bl[t]);
        }
    }
}

extern "C" void kernel_launch(void* const* d_in, const int* in_sizes, int n_in,
                              void* d_out, int out_size) {
    const float* x  = (const float*)d_in[0];
    const float* W1 = (const float*)d_in[1];
    const float* W2 = (const float*)d_in[2];
    const float* a1 = (const float*)d_in[3];
    const float* b1 = (const float*)d_in[4];
    const float* a2 = (const float*)d_in[5];
    const float* b2 = (const float*)d_in[6];
    const float* Wl = (const float*)d_in[7];
    const float* bl = (const float*)d_in[8];
    float* out = (float*)d_out;
    (void)in_sizes; (void)n_in; (void)out_size;

    cudaFuncSetAttribute(k_conv1, cudaFuncAttributeMaxDynamicSharedMemorySize, C1_SMEM);
    cudaFuncSetAttribute(k_conv2, cudaFuncAttributeMaxDynamicSharedMemorySize, C2_SMEM);

    k_filter_hash<<<1, 64>>>(W1, W2, a1, b1, a2, b2);
    k_xrows<<<BATCH * 3 * 4, 256>>>(x);
    k_q1mask<<<BATCH, 32>>>(a1, b1);
    k_conv1<<<BATCH * 43 * 2, 128, C1_SMEM>>>(x, W1);
    k_q2mask<<<BATCH, 160>>>(a2, b2);
    k_conv2<<<BATCH * 32 * 2, 512, C2_SMEM>>>(W2);
    k_linear<<<BATCH * 5 * 8, 256>>>(Wl, bl, out);
}

// round 6
// speedup vs baseline: 3.5000x; 1.0998x over previous
#include <cuda_runtime.h>
#include <cstdint>

#define BATCH 32
#define H0 260
#define W0 1004
#define H1 258
#define W1W 1002
#define H1P 1004
#define H2 256
#define W2W 1000
#define D1 27
#define D2 45

__device__ float g_h1[(size_t)BATCH * 5 * H1 * H1P];
__device__ float g_rsp[(size_t)BATCH * 5 * H1 * 2];   // per-half row partial sums
__device__ float g_re[(size_t)BATCH * 5 * H1 * 4];    // row edges e0,e1,e1000,e1001
__device__ float g_xrs[(size_t)BATCH * 3 * H0 * 3];
__device__ float g_pd[(size_t)BATCH * 5 * H2 * 2 * 10]; // linear partials per half
__device__ int   g_fh1[5];
__device__ int   g_fh2[5];
__device__ int   g_m1[BATCH * 5];
__device__ int   g_m2[BATCH * 5];

// ---------------- filter hashes (warp0: layer1, warp1: layer2) -------------
__global__ void k_filter_hash(const float* __restrict__ W1, const float* __restrict__ W2,
                              const float* __restrict__ a1, const float* __restrict__ b1,
                              const float* __restrict__ a2, const float* __restrict__ b2) {
    int t = threadIdx.x, lane = t & 31, wrp = t >> 5;
    const float* W = wrp ? W2 : W1;
    const float* a = wrp ? a2 : a1;
    float bb = wrp ? *b2 : *b1;
    int d = wrp ? D2 : D1;
    float ss = 0.f;
    if (lane < 5) for (int k = 0; k < d; ++k) { float v = W[lane * d + k]; ss += v * v; }
    float nrm = sqrtf(ss);
    for (int o = 16; o; o >>= 1) nrm = fmaxf(nrm, __shfl_xor_sync(0xffffffffu, nrm, o));
    float scale = 0.99f / nrm;
    if (lane < 5) {
        float dot = 0.f;
        for (int k = 0; k < d; ++k) dot += (W[lane * d + k] * scale) * a[k];
        float n2 = ss * scale * scale;
        float p2 = n2 * n2, p4 = p2 * p2, p8 = p4 * p4, p16 = p8 * p8;
        dot += n2 * a[d] + p2 * a[d + 1] + p4 * a[d + 2] + p8 * a[d + 3] + p16 * a[d + 4] + bb;
        int h = (int)floorf(dot / 0.1f);
        (wrp ? g_fh2 : g_fh1)[lane] = h & 1;
    }
}

// ---------------- x row restricted sums -> g_xrs ---------------------------
__global__ __launch_bounds__(256) void k_xrows(const float* __restrict__ x) {
    int blk = blockIdx.x, bc = blk >> 2, q = blk & 3;
    int r0 = q * 65;
    int tid = threadIdx.x, lane = tid & 31, wrp = tid >> 5;
    for (int r = r0 + wrp; r < r0 + 65; r += 8) {
        const float* row = x + ((size_t)bc * H0 + r) * W0;
        float s = 0.f;
        for (int col = lane; col < W0; col += 32) s += row[col];
        for (int o = 16; o; o >>= 1) s += __shfl_down_sync(0xffffffffu, s, o);
        if (lane == 0) {
            float e0 = row[0], e1 = row[1], ea = row[W0 - 2], eb = row[W0 - 1];
            float* outp = g_xrs + ((size_t)bc * H0 + r) * 3;
            outp[0] = s - ea - eb;
            outp[1] = s - e0 - eb;
            outp[2] = s - e0 - e1;
        }
    }
}

// ---------------- layer-1 query hash + mask --------------------------------
__global__ void k_q1mask(const float* __restrict__ a, const float* __restrict__ bp) {
    __shared__ float q[D1];
    int b = blockIdx.x, t = threadIdx.x;
    if (t < D1) {
        int c = t / 9, rem = t % 9, i = rem / 3, j = rem % 3;
        const float* base = g_xrs + ((size_t)(b * 3 + c) * H0) * 3;
        double s = 0.0;
        for (int r = i; r < i + 258; ++r) s += (double)base[r * 3 + j];
        q[t] = (float)(s / (258.0 * 1002.0));
    }
    __syncthreads();
    if (t == 0) {
        float ss = 0.f;
        for (int k = 0; k < D1; ++k) ss += q[k] * q[k];
        float inv = 1.0f / fmaxf(sqrtf(ss), 1e-12f);
        double dot = 0.0;
        for (int k = 0; k < D1; ++k) dot += (double)(q[k] * inv) * (double)a[k];
        dot += 0.5 * ((double)a[D1] + a[D1 + 1] + a[D1 + 2] + a[D1 + 3] + a[D1 + 4]) + (double)*bp;
        int qh = ((int)floor(dot / 0.1)) & 1;
        for (int c = 0; c < 5; ++c) g_m1[b * 5 + c] = (g_fh1[c] == qh) ? 1 : 0;
    }
}

// ---------------- conv1: 6 rows x half-width, 256 thr, 2 cols/thread -------
#define C1_SMEM (3 * 8 * 512 * 4)

__global__ __launch_bounds__(256, 4) void k_conv1(const float* __restrict__ x,
                                                  const float* __restrict__ W1) {
    extern __shared__ float xs[];            // [3][8][512]
    __shared__ float s_warp[8][6];
    __shared__ float sE[6][2];
    int bid = blockIdx.x;
    int b = bid / 86, rem2 = bid % 86;
    int g = rem2 >> 1, half = rem2 & 1;
    int i0 = g * 6, base = half * 500;
    int tid = threadIdx.x, lane = tid & 31, wrp = tid >> 5;

    for (int v = tid; v < 3 * 8 * 128; v += 256) {
        int cc = v >> 10, rm = v & 1023;
        int rr = rm >> 7, jj = rm & 127;
        int col = base + jj * 4;
        float4 val = make_float4(0.f, 0.f, 0.f, 0.f);
        if (col + 3 < W0)
            val = *(const float4*)&x[((size_t)(b * 3 + cc) * H0 + (i0 + rr)) * W0 + col];
        ((float4*)xs)[v] = val;
    }
    int m[5];
#pragma unroll
    for (int o = 0; o < 5; ++o) m[o] = g_m1[b * 5 + o];
    __syncthreads();

    int nvalid = half ? 251 : 250;           // half1 thread 250 -> cols 1000,1001
    bool valid = (tid < nvalid);
    int j0 = tid * 2;

    for (int o = 0; o < 5; ++o) {
        if (!m[o]) continue;
        float acc[6][2];
#pragma unroll
        for (int ri = 0; ri < 6; ++ri) { acc[ri][0] = 0.f; acc[ri][1] = 0.f; }
        if (valid) {
#pragma unroll
            for (int cc = 0; cc < 3; ++cc) {
                float wr[9];
#pragma unroll
                for (int k = 0; k < 9; ++k) wr[k] = __ldg(W1 + o * 27 + cc * 9 + k);
#pragma unroll
                for (int rr = 0; rr < 8; ++rr) {
                    const float* p = &xs[(cc * 8 + rr) * 512 + j0];
                    float2 A = *(const float2*)p;
                    float2 B = *(const float2*)(p + 2);
#pragma unroll
                    for (int di = 0; di < 3; ++di) {
                        int ri = rr - di;
                        if (ri >= 0 && ri < 6) {
                            float w0 = wr[di * 3 + 0], w1 = wr[di * 3 + 1], w2 = wr[di * 3 + 2];
                            acc[ri][0] += A.x * w0 + A.y * w1 + B.x * w2;
                            acc[ri][1] += A.y * w0 + B.x * w1 + B.y * w2;
                        }
                    }
                }
            }
        }
#pragma unroll
        for (int ri = 0; ri < 6; ++ri) {
            float r0 = fmaxf(acc[ri][0], 0.f), r1 = fmaxf(acc[ri][1], 0.f);
            float part = 0.f;
            if (valid) {
                size_t rowbase = ((size_t)(b * 5 + o) * H1 + (i0 + ri)) * H1P + base + j0;
                *(float2*)(g_h1 + rowbase) = make_float2(r0, r1);
                part = r0 + r1;
            }
            if (half == 0 && tid == 0)   { sE[ri][0] = r0; sE[ri][1] = r1; }
            if (half == 1 && tid == 250) { sE[ri][0] = r0; sE[ri][1] = r1; }
            for (int o2 = 16; o2; o2 >>= 1) part += __shfl_down_sync(0xffffffffu, part, o2);
            if (lane == 0) s_warp[wrp][ri] = part;
        }
        __syncthreads();
        if (tid < 6) {
            float full = 0.f;
#pragma unroll
            for (int k = 0; k < 8; ++k) full += s_warp[k][tid];
            size_t row = (size_t)(b * 5 + o) * H1 + (i0 + tid);
            g_rsp[row * 2 + half] = full;
            g_re[row * 4 + half * 2 + 0] = sE[tid][0];
            g_re[row * 4 + half * 2 + 1] = sE[tid][1];
        }
        __syncthreads();
    }
}

// ---------------- layer-2 query hash + mask --------------------------------
__global__ void k_q2mask(const float* __restrict__ a, const float* __restrict__ bp) {
    __shared__ float q[D2];
    int b = blockIdx.x, tid = threadIdx.x, lane = tid & 31, c = tid >> 5;
    if (c < 5) {
        if (!g_m1[b * 5 + c]) {
            if (lane < 9) q[c * 9 + lane] = 0.f;
        } else {
            const float* P = g_rsp + (size_t)(b * 5 + c) * H1 * 2;
            const float* E = g_re + (size_t)(b * 5 + c) * H1 * 4;
            double F = 0.0, E0 = 0.0, E1 = 0.0, EA = 0.0, EB = 0.0;
            for (int r = lane; r < H1; r += 32) {
                F  += (double)P[r * 2 + 0] + (double)P[r * 2 + 1];
                E0 += (double)E[r * 4 + 0];
                E1 += (double)E[r * 4 + 1];
                EA += (double)E[r * 4 + 2];
                EB += (double)E[r * 4 + 3];
            }
            for (int o = 16; o; o >>= 1) {
                F  += __shfl_down_sync(0xffffffffu, F, o);
                E0 += __shfl_down_sync(0xffffffffu, E0, o);
                E1 += __shfl_down_sync(0xffffffffu, E1, o);
                EA += __shfl_down_sync(0xffffffffu, EA, o);
                EB += __shfl_down_sync(0xffffffffu, EB, o);
            }
            if (lane == 0) {
                double tot[3] = {F - EA - EB, F - E0 - EB, F - E0 - E1};
                const int rows[4] = {0, 1, 256, 257};
                double rsv[4][3];
                for (int k = 0; k < 4; ++k) {
                    int r = rows[k];
                    double fr = (double)P[r * 2 + 0] + (double)P[r * 2 + 1];
                    double e0 = E[r * 4 + 0], e1 = E[r * 4 + 1];
                    double ea = E[r * 4 + 2], eb = E[r * 4 + 3];
                    rsv[k][0] = fr - ea - eb;
                    rsv[k][1] = fr - e0 - eb;
                    rsv[k][2] = fr - e0 - e1;
                }
                const int exA[3] = {2, 0, 0};
                const int exB[3] = {3, 3, 1};
                for (int i = 0; i < 3; ++i)
                    for (int jo = 0; jo < 3; ++jo)
                        q[c * 9 + i * 3 + jo] =
                            (float)((tot[jo] - rsv[exA[i]][jo] - rsv[exB[i]][jo]) / 256000.0);
            }
        }
    }
    __syncthreads();
    if (tid == 0) {
        float ss = 0.f;
        for (int k = 0; k < D2; ++k) ss += q[k] * q[k];
        float inv = 1.0f / fmaxf(sqrtf(ss), 1e-12f);
        double dot = 0.0;
        for (int k = 0; k < D2; ++k) dot += (double)(q[k] * inv) * (double)a[k];
        dot += 0.5 * ((double)a[D2] + a[D2 + 1] + a[D2 + 2] + a[D2 + 3] + a[D2 + 4]) + (double)*bp;
        int qh = ((int)floor(dot / 0.1)) & 1;
        for (int cc = 0; cc < 5; ++cc) g_m2[b * 5 + cc] = (g_fh2[cc] == qh) ? 1 : 0;
    }
}

// ---------------- conv2 + relu + fused linear partials ---------------------
#define C2_SMEM (5 * 10 * 512 * 4)

__global__ __launch_bounds__(512, 2) void k_conv2pd(const float* __restrict__ W2,
                                                    const float* __restrict__ Wl) {
    extern __shared__ float ts[];             // [na][10][512]
    __shared__ float sred[16][10];
    __shared__ int clist[5], m2s[5], s_na;
    int bid = blockIdx.x;
    int b = bid >> 6, rem2 = bid & 63;
    int g = rem2 >> 1, half = rem2 & 1;
    int i0 = g * 8, base = half * 500;
    int tid = threadIdx.x, lane = tid & 31, wid = tid >> 5;
    if (tid == 0) {
        int na = 0;
        for (int c = 0; c < 5; ++c) if (g_m1[b * 5 + c]) clist[na++] = c;
        s_na = na;
    }
    if (tid < 5) m2s[tid] = g_m2[b * 5 + tid];
    __syncthreads();
    int na = s_na;
    for (int v = tid; v < na * 10 * 128; v += 512) {
        int s = v / 1280, rm = v - s * 1280;
        int rr = rm >> 7, jj = rm & 127;
        int col = base + jj * 4;
        float4 val = make_float4(0.f, 0.f, 0.f, 0.f);
        if (col + 3 < H1P)
            val = *(const float4*)&g_h1[((size_t)(b * 5 + clist[s]) * H1 + (i0 + rr)) * H1P + col];
        ((float4*)ts)[v] = val;
    }
    __syncthreads();
    int quad = tid >> 7, t2 = tid & 127;
    int rbase = quad * 2;
    int j0 = t2 * 4;
    bool valid = (t2 < 125);
    for (int o = 0; o < 5; ++o) {
        if (!m2s[o]) continue;
        float acc[2][4];
#pragma unroll
        for (int ri = 0; ri < 2; ++ri)
#pragma unroll
            for (int k = 0; k < 4; ++k) acc[ri][k] = 0.f;
        if (valid) {
            for (int s = 0; s < na; ++s) {
                float wr[9];
#pragma unroll
                for (int k = 0; k < 9; ++k) wr[k] = __ldg(&W2[o * 45 + clist[s] * 9 + k]);
#pragma unroll
                for (int rr = 0; rr < 4; ++rr) {
                    const float* p = &ts[(s * 10 + rbase + rr) * 512 + j0];
                    float4 v4 = *(const float4*)p;
                    float2 v2 = *(const float2*)(p + 4);
#pragma unroll
                    for (int di = 0; di < 3; ++di) {
                        int ri = rr - di;
                        if (ri >= 0 && ri < 2) {
                            float w0 = wr[di * 3 + 0], w1 = wr[di * 3 + 1], w2 = wr[di * 3 + 2];
                            acc[ri][0] += v4.x * w0 + v4.y * w1 + v4.z * w2;
                            acc[ri][1] += v4.y * w0 + v4.z * w1 + v4.w * w2;
                            acc[ri][2] += v4.z * w0 + v4.w * w1 + v2.x * w2;
                            acc[ri][3] += v4.w * w0 + v2.x * w1 + v2.y * w2;
                        }
                    }
                }
            }
        }
        // fused linear: per row, 10 partial dots over this half's 500 cols
#pragma unroll
        for (int ri = 0; ri < 2; ++ri) {
            float h0 = fmaxf(acc[ri][0], 0.f), h1v = fmaxf(acc[ri][1], 0.f);
            float h2v = fmaxf(acc[ri][2], 0.f), h3 = fmaxf(acc[ri][3], 0.f);
#pragma unroll
            for (int t = 0; t < 10; ++t) {
                float v = 0.f;
                if (valid) {
                    float4 wl = __ldg((const float4*)&Wl[t * 1000 + base + j0]);
                    v = h0 * wl.x + h1v * wl.y + h2v * wl.z + h3 * wl.w;
                }
                for (int o2 = 16; o2; o2 >>= 1) v += __shfl_down_sync(0xffffffffu, v, o2);
                if (lane == 0) sred[wid][t] = v;
            }
            __syncthreads();
            if (t2 < 10) {
                float p = sred[quad * 4 + 0][t2] + sred[quad * 4 + 1][t2] +
                          sred[quad * 4 + 2][t2] + sred[quad * 4 + 3][t2];
                int row = i0 + rbase + ri;
                g_pd[(((size_t)(b * 5 + o) * H2 + row) * 2 + half) * 10 + t2] = p;
            }
            __syncthreads();
        }
    }
}

// ---------------- combine partials + bias -> out ---------------------------
__global__ __launch_bounds__(256) void k_combine(const float* __restrict__ bl,
                                                 float* __restrict__ out) {
    int bc = blockIdx.x;
    int row = threadIdx.x;
    int m = g_m2[bc];
    size_t obase = ((size_t)bc * H2 + row) * 10;
    size_t pbase = ((size_t)bc * H2 + row) * 20;
#pragma unroll
    for (int t = 0; t < 10; ++t) {
        float v = __ldg(&bl[t]);
        if (m) v += g_pd[pbase + t] + g_pd[pbase + 10 + t];
        out[obase + t] = v;
    }
}

extern "C" void kernel_launch(void* const* d_in, const int* in_sizes, int n_in,
                              void* d_out, int out_size) {
    const float* x  = (const float*)d_in[0];
    const float* W1 = (const float*)d_in[1];
    const float* W2 = (const float*)d_in[2];
    const float* a1 = (const float*)d_in[3];
    const float* b1 = (const float*)d_in[4];
    const float* a2 = (const float*)d_in[5];
    const float* b2 = (const float*)d_in[6];
    const float* Wl = (const float*)d_in[7];
    const float* bl = (const float*)d_in[8];
    float* out = (float*)d_out;
    (void)in_sizes; (void)n_in; (void)out_size;

    cudaFuncSetAttribute(k_conv1, cudaFuncAttributeMaxDynamicSharedMemorySize, C1_SMEM);
    cudaFuncSetAttribute(k_conv2pd, cudaFuncAttributeMaxDynamicSharedMemorySize, C2_SMEM);

    k_filter_hash<<<1, 64>>>(W1, W2, a1, b1, a2, b2);
    k_xrows<<<BATCH * 3 * 4, 256>>>(x);
    k_q1mask<<<BATCH, 32>>>(a1, b1);
    k_conv1<<<BATCH * 43 * 2, 256, C1_SMEM>>>(x, W1);
    k_q2mask<<<BATCH, 160>>>(a2, b2);
    k_conv2pd<<<BATCH * 32 * 2, 512, C2_SMEM>>>(W2, Wl);
    k_combine<<<BATCH * 5, 256>>>(bl, out);
}

// round 7
// speedup vs baseline: 3.7419x; 1.0691x over previous
#include <cuda_runtime.h>
#include <cstdint>

#define BATCH 32
#define H0 260
#define W0 1004
#define H1 258
#define W1W 1002
#define H1P 1004
#define H2 256
#define W2W 1000
#define D1 27
#define D2 45

__device__ float g_h1[(size_t)BATCH * 5 * H1 * H1P];
__device__ float g_rsp[(size_t)BATCH * 5 * H1 * 2];
__device__ float g_re[(size_t)BATCH * 5 * H1 * 4];
__device__ float g_xrs[(size_t)BATCH * 3 * H0 * 3];
__device__ float g_pd[(size_t)BATCH * 5 * H2 * 2 * 10];
__device__ int   g_fh1[5];
__device__ int   g_fh2[5];
__device__ int   g_m1[BATCH * 5];
__device__ int   g_m2[BATCH * 5];

// ---------------- filter hashes ---------------------------------------------
__global__ void k_filter_hash(const float* __restrict__ W1, const float* __restrict__ W2,
                              const float* __restrict__ a1, const float* __restrict__ b1,
                              const float* __restrict__ a2, const float* __restrict__ b2) {
    int t = threadIdx.x, lane = t & 31, wrp = t >> 5;
    const float* W = wrp ? W2 : W1;
    const float* a = wrp ? a2 : a1;
    float bb = wrp ? *b2 : *b1;
    int d = wrp ? D2 : D1;
    float ss = 0.f;
    if (lane < 5) for (int k = 0; k < d; ++k) { float v = W[lane * d + k]; ss += v * v; }
    float nrm = sqrtf(ss);
    for (int o = 16; o; o >>= 1) nrm = fmaxf(nrm, __shfl_xor_sync(0xffffffffu, nrm, o));
    float scale = 0.99f / nrm;
    if (lane < 5) {
        float dot = 0.f;
        for (int k = 0; k < d; ++k) dot += (W[lane * d + k] * scale) * a[k];
        float n2 = ss * scale * scale;
        float p2 = n2 * n2, p4 = p2 * p2, p8 = p4 * p4, p16 = p8 * p8;
        dot += n2 * a[d] + p2 * a[d + 1] + p4 * a[d + 2] + p8 * a[d + 3] + p16 * a[d + 4] + bb;
        int h = (int)floorf(dot / 0.1f);
        (wrp ? g_fh2 : g_fh1)[lane] = h & 1;
    }
}

// ---------------- x row restricted sums -------------------------------------
__global__ __launch_bounds__(256) void k_xrows(const float* __restrict__ x) {
    int blk = blockIdx.x, bc = blk >> 2, q = blk & 3;
    int r0 = q * 65;
    int tid = threadIdx.x, lane = tid & 31, wrp = tid >> 5;
    for (int r = r0 + wrp; r < r0 + 65; r += 8) {
        const float* row = x + ((size_t)bc * H0 + r) * W0;
        float s = 0.f;
        for (int col = lane; col < W0; col += 32) s += row[col];
        for (int o = 16; o; o >>= 1) s += __shfl_down_sync(0xffffffffu, s, o);
        if (lane == 0) {
            float e0 = row[0], e1 = row[1], ea = row[W0 - 2], eb = row[W0 - 1];
            float* outp = g_xrs + ((size_t)bc * H0 + r) * 3;
            outp[0] = s - ea - eb;
            outp[1] = s - e0 - eb;
            outp[2] = s - e0 - e1;
        }
    }
}

// ---------------- layer-1 query hash + mask ---------------------------------
__global__ void k_q1mask(const float* __restrict__ a, const float* __restrict__ bp) {
    __shared__ float q[D1];
    int b = blockIdx.x, t = threadIdx.x;
    if (t < D1) {
        int c = t / 9, rem = t % 9, i = rem / 3, j = rem % 3;
        const float* base = g_xrs + ((size_t)(b * 3 + c) * H0) * 3;
        double s = 0.0;
        for (int r = i; r < i + 258; ++r) s += (double)base[r * 3 + j];
        q[t] = (float)(s / (258.0 * 1002.0));
    }
    __syncthreads();
    if (t == 0) {
        float ss = 0.f;
        for (int k = 0; k < D1; ++k) ss += q[k] * q[k];
        float inv = 1.0f / fmaxf(sqrtf(ss), 1e-12f);
        double dot = 0.0;
        for (int k = 0; k < D1; ++k) dot += (double)(q[k] * inv) * (double)a[k];
        dot += 0.5 * ((double)a[D1] + a[D1 + 1] + a[D1 + 2] + a[D1 + 3] + a[D1 + 4]) + (double)*bp;
        int qh = ((int)floor(dot / 0.1)) & 1;
        for (int c = 0; c < 5; ++c) g_m1[b * 5 + c] = (g_fh1[c] == qh) ? 1 : 0;
    }
}

// ---------------- conv1: 6 rows x half-width, 2 channels per pass ----------
#define C1_SMEM (3 * 8 * 512 * 4)

__global__ __launch_bounds__(128, 4) void k_conv1(const float* __restrict__ x,
                                                  const float* __restrict__ W1) {
    extern __shared__ float xs[];            // [3][8][512]
    __shared__ float s_warp[4][6][2];
    __shared__ float sE[6][2][2];
    __shared__ int cl1[5], s_na;
    int bid = blockIdx.x;
    int b = bid / 86, rem2 = bid % 86;
    int g = rem2 >> 1, half = rem2 & 1;
    int i0 = g * 6, base = half * 500;
    int tid = threadIdx.x, lane = tid & 31, wrp = tid >> 5;

    if (tid == 0) {
        int na = 0;
        for (int c = 0; c < 5; ++c) if (g_m1[b * 5 + c]) cl1[na++] = c;
        s_na = na;
    }
    for (int v = tid; v < 3 * 8 * 128; v += 128) {
        int cc = v >> 10, rm = v & 1023;
        int rr = rm >> 7, jj = rm & 127;
        int col = base + jj * 4;
        float4 val = make_float4(0.f, 0.f, 0.f, 0.f);
        if (col + 3 < W0)
            val = *(const float4*)&x[((size_t)(b * 3 + cc) * H0 + (i0 + rr)) * W0 + col];
        ((float4*)xs)[v] = val;
    }
    __syncthreads();
    int na = s_na;
    bool tail = (half == 1 && tid == 125);
    bool valid = (tid < 125) || tail;
    int j0 = tid * 4;

    for (int p = 0; p < (na + 1) / 2; ++p) {
        int o0 = cl1[2 * p];
        int o1 = (2 * p + 1 < na) ? cl1[2 * p + 1] : -1;
        int o1w = (o1 >= 0) ? o1 : o0;
        float acc0[6][4], acc1[6][4];
#pragma unroll
        for (int ri = 0; ri < 6; ++ri)
#pragma unroll
            for (int k = 0; k < 4; ++k) { acc0[ri][k] = 0.f; acc1[ri][k] = 0.f; }
        if (valid) {
#pragma unroll
            for (int cc = 0; cc < 3; ++cc) {
                float w0r[9], w1r[9];
#pragma unroll
                for (int k = 0; k < 9; ++k) {
                    w0r[k] = __ldg(W1 + o0 * 27 + cc * 9 + k);
                    w1r[k] = __ldg(W1 + o1w * 27 + cc * 9 + k);
                }
#pragma unroll
                for (int rr = 0; rr < 8; ++rr) {
                    const float* ptr = &xs[(cc * 8 + rr) * 512 + j0];
                    float4 v4 = *(const float4*)ptr;
                    float2 v2 = *(const float2*)(ptr + 4);
#pragma unroll
                    for (int di = 0; di < 3; ++di) {
                        int ri = rr - di;
                        if (ri >= 0 && ri < 6) {
                            float a0 = w0r[di * 3 + 0], a1 = w0r[di * 3 + 1], a2 = w0r[di * 3 + 2];
                            acc0[ri][0] += v4.x * a0 + v4.y * a1 + v4.z * a2;
                            acc0[ri][1] += v4.y * a0 + v4.z * a1 + v4.w * a2;
                            acc0[ri][2] += v4.z * a0 + v4.w * a1 + v2.x * a2;
                            acc0[ri][3] += v4.w * a0 + v2.x * a1 + v2.y * a2;
                            float b0 = w1r[di * 3 + 0], b1 = w1r[di * 3 + 1], b2 = w1r[di * 3 + 2];
                            acc1[ri][0] += v4.x * b0 + v4.y * b1 + v4.z * b2;
                            acc1[ri][1] += v4.y * b0 + v4.z * b1 + v4.w * b2;
                            acc1[ri][2] += v4.z * b0 + v4.w * b1 + v2.x * b2;
                            acc1[ri][3] += v4.w * b0 + v2.x * b1 + v2.y * b2;
                        }
                    }
                }
            }
        }
#pragma unroll
        for (int ri = 0; ri < 6; ++ri) {
            float p00 = fmaxf(acc0[ri][0], 0.f), p01 = fmaxf(acc0[ri][1], 0.f);
            float p02 = fmaxf(acc0[ri][2], 0.f), p03 = fmaxf(acc0[ri][3], 0.f);
            float p10 = fmaxf(acc1[ri][0], 0.f), p11 = fmaxf(acc1[ri][1], 0.f);
            float p12 = fmaxf(acc1[ri][2], 0.f), p13 = fmaxf(acc1[ri][3], 0.f);
            float part0 = 0.f, part1 = 0.f;
            if (valid) {
                size_t r0b = ((size_t)(b * 5 + o0) * H1 + (i0 + ri)) * H1P + base + j0;
                if (!tail) {
                    *(float4*)(g_h1 + r0b) = make_float4(p00, p01, p02, p03);
                    part0 = p00 + p01 + p02 + p03;
                } else {
                    g_h1[r0b + 0] = p00; g_h1[r0b + 1] = p01;
                    part0 = p00 + p01;
                }
                if (o1 >= 0) {
                    size_t r1b = ((size_t)(b * 5 + o1) * H1 + (i0 + ri)) * H1P + base + j0;
                    if (!tail) {
                        *(float4*)(g_h1 + r1b) = make_float4(p10, p11, p12, p13);
                        part1 = p10 + p11 + p12 + p13;
                    } else {
                        g_h1[r1b + 0] = p10; g_h1[r1b + 1] = p11;
                        part1 = p10 + p11;
                    }
                }
            }
            if ((half == 0 && tid == 0) || (half == 1 && tid == 125)) {
                sE[ri][0][0] = p00; sE[ri][1][0] = p01;
                sE[ri][0][1] = p10; sE[ri][1][1] = p11;
            }
            for (int o2 = 16; o2; o2 >>= 1) {
                part0 += __shfl_down_sync(0xffffffffu, part0, o2);
                part1 += __shfl_down_sync(0xffffffffu, part1, o2);
            }
            if (lane == 0) { s_warp[wrp][ri][0] = part0; s_warp[wrp][ri][1] = part1; }
        }
        __syncthreads();
        if (tid < 12) {
            int ch = tid / 6, r = tid % 6;
            int oc = ch ? o1 : o0;
            if (oc >= 0) {
                float full = s_warp[0][r][ch] + s_warp[1][r][ch] +
                             s_warp[2][r][ch] + s_warp[3][r][ch];
                size_t row = (size_t)(b * 5 + oc) * H1 + (i0 + r);
                g_rsp[row * 2 + half] = full;
                g_re[row * 4 + half * 2 + 0] = sE[r][0][ch];
                g_re[row * 4 + half * 2 + 1] = sE[r][1][ch];
            }
        }
        __syncthreads();
    }
}

// ---------------- layer-2 query hash + mask ---------------------------------
__global__ void k_q2mask(const float* __restrict__ a, const float* __restrict__ bp) {
    __shared__ float q[D2];
    int b = blockIdx.x, tid = threadIdx.x, lane = tid & 31, c = tid >> 5;
    if (c < 5) {
        if (!g_m1[b * 5 + c]) {
            if (lane < 9) q[c * 9 + lane] = 0.f;
        } else {
            const float* P = g_rsp + (size_t)(b * 5 + c) * H1 * 2;
            const float* E = g_re + (size_t)(b * 5 + c) * H1 * 4;
            double F = 0.0, E0 = 0.0, E1 = 0.0, EA = 0.0, EB = 0.0;
            for (int r = lane; r < H1; r += 32) {
                F  += (double)P[r * 2 + 0] + (double)P[r * 2 + 1];
                E0 += (double)E[r * 4 + 0];
                E1 += (double)E[r * 4 + 1];
                EA += (double)E[r * 4 + 2];
                EB += (double)E[r * 4 + 3];
            }
            for (int o = 16; o; o >>= 1) {
                F  += __shfl_down_sync(0xffffffffu, F, o);
                E0 += __shfl_down_sync(0xffffffffu, E0, o);
                E1 += __shfl_down_sync(0xffffffffu, E1, o);
                EA += __shfl_down_sync(0xffffffffu, EA, o);
                EB += __shfl_down_sync(0xffffffffu, EB, o);
            }
            if (lane == 0) {
                double tot[3] = {F - EA - EB, F - E0 - EB, F - E0 - E1};
                const int rows[4] = {0, 1, 256, 257};
                double rsv[4][3];
                for (int k = 0; k < 4; ++k) {
                    int r = rows[k];
                    double fr = (double)P[r * 2 + 0] + (double)P[r * 2 + 1];
                    double e0 = E[r * 4 + 0], e1 = E[r * 4 + 1];
                    double ea = E[r * 4 + 2], eb = E[r * 4 + 3];
                    rsv[k][0] = fr - ea - eb;
                    rsv[k][1] = fr - e0 - eb;
                    rsv[k][2] = fr - e0 - e1;
                }
                const int exA[3] = {2, 0, 0};
                const int exB[3] = {3, 3, 1};
                for (int i = 0; i < 3; ++i)
                    for (int jo = 0; jo < 3; ++jo)
                        q[c * 9 + i * 3 + jo] =
                            (float)((tot[jo] - rsv[exA[i]][jo] - rsv[exB[i]][jo]) / 256000.0);
            }
        }
    }
    __syncthreads();
    if (tid == 0) {
        float ss = 0.f;
        for (int k = 0; k < D2; ++k) ss += q[k] * q[k];
        float inv = 1.0f / fmaxf(sqrtf(ss), 1e-12f);
        double dot = 0.0;
        for (int k = 0; k < D2; ++k) dot += (double)(q[k] * inv) * (double)a[k];
        dot += 0.5 * ((double)a[D2] + a[D2 + 1] + a[D2 + 2] + a[D2 + 3] + a[D2 + 4]) + (double)*bp;
        int qh = ((int)floor(dot / 0.1)) & 1;
        for (int cc = 0; cc < 5; ++cc) g_m2[b * 5 + cc] = (g_fh2[cc] == qh) ? 1 : 0;
    }
}

// ---------------- conv2 + relu + fused linear, 2 channels per pass ---------
#define C2_SMEM (5 * 10 * 512 * 4)

__global__ __launch_bounds__(512, 2) void k_conv2pd(const float* __restrict__ W2,
                                                    const float* __restrict__ Wl) {
    extern __shared__ float ts[];             // [na][10][512]
    __shared__ float sred[16][10][2];
    __shared__ int cl[5], cl2[5], s_na, s_na2;
    int bid = blockIdx.x;
    int b = bid >> 6, rem2 = bid & 63;
    int g = rem2 >> 1, half = rem2 & 1;
    int i0 = g * 8, base = half * 500;
    int tid = threadIdx.x, lane = tid & 31, wid = tid >> 5;
    if (tid == 0) {
        int na = 0;
        for (int c = 0; c < 5; ++c) if (g_m1[b * 5 + c]) cl[na++] = c;
        s_na = na;
        int na2 = 0;
        for (int c = 0; c < 5; ++c) if (g_m2[b * 5 + c]) cl2[na2++] = c;
        s_na2 = na2;
    }
    __syncthreads();
    int na = s_na, na2 = s_na2;
    for (int v = tid; v < na * 10 * 128; v += 512) {
        int s = v / 1280, rm = v - s * 1280;
        int rr = rm >> 7, jj = rm & 127;
        int col = base + jj * 4;
        float4 val = make_float4(0.f, 0.f, 0.f, 0.f);
        if (col + 3 < H1P)
            val = *(const float4*)&g_h1[((size_t)(b * 5 + cl[s]) * H1 + (i0 + rr)) * H1P + col];
        ((float4*)ts)[v] = val;
    }
    __syncthreads();
    int quad = tid >> 7, t2 = tid & 127;
    int rbase = quad * 2;
    int j0 = t2 * 4;
    bool valid = (t2 < 125);
    for (int p = 0; p < (na2 + 1) / 2; ++p) {
        int o0 = cl2[2 * p];
        int o1 = (2 * p + 1 < na2) ? cl2[2 * p + 1] : -1;
        int o1w = (o1 >= 0) ? o1 : o0;
        float acc0[2][4], acc1[2][4];
#pragma unroll
        for (int ri = 0; ri < 2; ++ri)
#pragma unroll
            for (int k = 0; k < 4; ++k) { acc0[ri][k] = 0.f; acc1[ri][k] = 0.f; }
        if (valid) {
            for (int s = 0; s < na; ++s) {
                float w0r[9], w1r[9];
#pragma unroll
                for (int k = 0; k < 9; ++k) {
                    w0r[k] = __ldg(&W2[o0 * 45 + cl[s] * 9 + k]);
                    w1r[k] = __ldg(&W2[o1w * 45 + cl[s] * 9 + k]);
                }
#pragma unroll
                for (int rr = 0; rr < 4; ++rr) {
                    const float* ptr = &ts[(s * 10 + rbase + rr) * 512 + j0];
                    float4 v4 = *(const float4*)ptr;
                    float2 v2 = *(const float2*)(ptr + 4);
#pragma unroll
                    for (int di = 0; di < 3; ++di) {
                        int ri = rr - di;
                        if (ri >= 0 && ri < 2) {
                            float a0 = w0r[di * 3 + 0], a1 = w0r[di * 3 + 1], a2 = w0r[di * 3 + 2];
                            acc0[ri][0] += v4.x * a0 + v4.y * a1 + v4.z * a2;
                            acc0[ri][1] += v4.y * a0 + v4.z * a1 + v4.w * a2;
                            acc0[ri][2] += v4.z * a0 + v4.w * a1 + v2.x * a2;
                            acc0[ri][3] += v4.w * a0 + v2.x * a1 + v2.y * a2;
                            float b0 = w1r[di * 3 + 0], b1 = w1r[di * 3 + 1], b2 = w1r[di * 3 + 2];
                            acc1[ri][0] += v4.x * b0 + v4.y * b1 + v4.z * b2;
                            acc1[ri][1] += v4.y * b0 + v4.z * b1 + v4.w * b2;
                            acc1[ri][2] += v4.z * b0 + v4.w * b1 + v2.x * b2;
                            acc1[ri][3] += v4.w * b0 + v2.x * b1 + v2.y * b2;
                        }
                    }
                }
            }
        }
#pragma unroll
        for (int ri = 0; ri < 2; ++ri) {
            float h00 = fmaxf(acc0[ri][0], 0.f), h01 = fmaxf(acc0[ri][1], 0.f);
            float h02 = fmaxf(acc0[ri][2], 0.f), h03 = fmaxf(acc0[ri][3], 0.f);
            float h10 = fmaxf(acc1[ri][0], 0.f), h11 = fmaxf(acc1[ri][1], 0.f);
            float h12 = fmaxf(acc1[ri][2], 0.f), h13 = fmaxf(acc1[ri][3], 0.f);
#pragma unroll
            for (int t = 0; t < 10; ++t) {
                float v0 = 0.f, v1 = 0.f;
                if (valid) {
                    float4 wl = __ldg((const float4*)&Wl[t * 1000 + base + j0]);
                    v0 = h00 * wl.x + h01 * wl.y + h02 * wl.z + h03 * wl.w;
                    v1 = h10 * wl.x + h11 * wl.y + h12 * wl.z + h13 * wl.w;
                }
                for (int o2 = 16; o2; o2 >>= 1) {
                    v0 += __shfl_down_sync(0xffffffffu, v0, o2);
                    v1 += __shfl_down_sync(0xffffffffu, v1, o2);
                }
                if (lane == 0) { sred[wid][t][0] = v0; sred[wid][t][1] = v1; }
            }
            __syncthreads();
            if (t2 < 10) {
                int row = i0 + rbase + ri;
                float p0 = sred[quad * 4 + 0][t2][0] + sred[quad * 4 + 1][t2][0] +
                           sred[quad * 4 + 2][t2][0] + sred[quad * 4 + 3][t2][0];
                g_pd[(((size_t)(b * 5 + o0) * H2 + row) * 2 + half) * 10 + t2] = p0;
                if (o1 >= 0) {
                    float p1 = sred[quad * 4 + 0][t2][1] + sred[quad * 4 + 1][t2][1] +
                               sred[quad * 4 + 2][t2][1] + sred[quad * 4 + 3][t2][1];
                    g_pd[(((size_t)(b * 5 + o1) * H2 + row) * 2 + half) * 10 + t2] = p1;
                }
            }
            __syncthreads();
        }
    }
}

// ---------------- combine partials + bias -> out ----------------------------
__global__ __launch_bounds__(256) void k_combine(const float* __restrict__ bl,
                                                 float* __restrict__ out) {
    int bc = blockIdx.x;
    int row = threadIdx.x;
    int m = g_m2[bc];
    size_t obase = ((size_t)bc * H2 + row) * 10;
    size_t pbase = ((size_t)bc * H2 + row) * 20;
#pragma unroll
    for (int t = 0; t < 10; ++t) {
        float v = __ldg(&bl[t]);
        if (m) v += g_pd[pbase + t] + g_pd[pbase + 10 + t];
        out[obase + t] = v;
    }
}

extern "C" void kernel_launch(void* const* d_in, const int* in_sizes, int n_in,
                              void* d_out, int out_size) {
    const float* x  = (const float*)d_in[0];
    const float* W1 = (const float*)d_in[1];
    const float* W2 = (const float*)d_in[2];
    const float* a1 = (const float*)d_in[3];
    const float* b1 = (const float*)d_in[4];
    const float* a2 = (const float*)d_in[5];
    const float* b2 = (const float*)d_in[6];
    const float* Wl = (const float*)d_in[7];
    const float* bl = (const float*)d_in[8];
    float* out = (float*)d_out;
    (void)in_sizes; (void)n_in; (void)out_size;

    cudaFuncSetAttribute(k_conv1, cudaFuncAttributeMaxDynamicSharedMemorySize, C1_SMEM);
    cudaFuncSetAttribute(k_conv2pd, cudaFuncAttributeMaxDynamicSharedMemorySize, C2_SMEM);

    k_filter_hash<<<1, 64>>>(W1, W2, a1, b1, a2, b2);
    k_xrows<<<BATCH * 3 * 4, 256>>>(x);
    k_q1mask<<<BATCH, 32>>>(a1, b1);
    k_conv1<<<BATCH * 43 * 2, 128, C1_SMEM>>>(x, W1);
    k_q2mask<<<BATCH, 160>>>(a2, b2);
    k_conv2pd<<<BATCH * 32 * 2, 512, C2_SMEM>>>(W2, Wl);
    k_combine<<<BATCH * 5, 256>>>(bl, out);
}